// round 16
// baseline (speedup 1.0000x reference)
#include <cuda_runtime.h>
#include <cuda.h>
#include <cstddef>

#define FFT_N 8192
#define NT    1024
#define CH    64

// XOR swizzle on float2 index: conflict-free (<=2-way worst case) for all
// access patterns used here.
#define SWZ(a) ((a) ^ (((a) >> 4) & 15))

// Named barrier over one 512-thread half (ids 1 and 2; id 0 = __syncthreads).
#define BARH(half) asm volatile("bar.sync %0, %1;" :: "r"(1 + (half)), "r"(512) : "memory")

#define PI_OVER_4096 7.66990393942820615e-4f

// ---- smem layout for the TMA kernel (bytes) --------------------------------
// [0, 65536)          b0
// [65536, 131072)     b1
// [131072, 163840)    staging: 2 bufs x 1024 float4 (512 lo rows + 512 hi rows)
// [163840, 163856)    mbar[2]
#define SM_STAGE_OFF 131072
#define SM_MBAR_OFF  163840
#define SM_TMA_TOTAL 163872

__device__ __forceinline__ float2 cmul(float2 a, float2 b) {
    return make_float2(fmaf(a.x, b.x, -a.y * b.y), fmaf(a.x, b.y, a.y * b.x));
}
__device__ __forceinline__ float2 cadd(float2 a, float2 b) { return make_float2(a.x + b.x, a.y + b.y); }
__device__ __forceinline__ float2 csub(float2 a, float2 b) { return make_float2(a.x - b.x, a.y - b.y); }

template<int DIR>
__device__ __forceinline__ void dft4(float2& a, float2& b, float2& c, float2& d) {
    float2 t0 = cadd(a, c), t1 = csub(a, c);
    float2 t2 = cadd(b, d), t3 = csub(b, d);
    a = cadd(t0, t2);
    c = csub(t0, t2);
    if (DIR > 0) {
        b = make_float2(t1.x + t3.y, t1.y - t3.x);
        d = make_float2(t1.x - t3.y, t1.y + t3.x);
    } else {
        b = make_float2(t1.x - t3.y, t1.y + t3.x);
        d = make_float2(t1.x + t3.y, t1.y - t3.x);
    }
}

template<int DIR>
__device__ __forceinline__ void dft16(float2 v[16]) {
    #pragma unroll
    for (int n1 = 0; n1 < 4; n1++)
        dft4<DIR>(v[n1], v[n1 + 4], v[n1 + 8], v[n1 + 12]);
    const float C1 = 0.92387953251128674f;
    const float S1 = 0.38268343236508978f;
    const float C2 = 0.70710678118654752f;
    const float s  = (DIR > 0) ? 1.0f : -1.0f;
    v[5]  = cmul(v[5],  make_float2( C1, -s * S1));
    v[6]  = cmul(v[6],  make_float2( C2, -s * C2));
    v[7]  = cmul(v[7],  make_float2( S1, -s * C1));
    v[9]  = cmul(v[9],  make_float2( C2, -s * C2));
    v[10] = cmul(v[10], make_float2(0.f, -s      ));
    v[11] = cmul(v[11], make_float2(-C2, -s * C2));
    v[13] = cmul(v[13], make_float2( S1, -s * C1));
    v[14] = cmul(v[14], make_float2(-C2, -s * C2));
    v[15] = cmul(v[15], make_float2(-C1,  s * S1));
    #pragma unroll
    for (int k2 = 0; k2 < 4; k2++)
        dft4<DIR>(v[4 * k2], v[4 * k2 + 1], v[4 * k2 + 2], v[4 * k2 + 3]);
}

// One in-place radix-16 Stockham DIT stage, half-CTA per pair.
template<int S, int DIR>
__device__ __forceinline__ void stage16_pair(float2* __restrict__ b0,
                                             float2* __restrict__ b1,
                                             int tid, bool p0, bool p1) {
    const int  half = tid >> 9;
    const int  j    = tid & 511;
    float2*    buf  = half ? b1 : b0;
    const bool act  = half ? p1 : p0;
    float2 v[16];
    if (act) {
        #pragma unroll
        for (int r = 0; r < 16; r++)
            v[r] = buf[SWZ(j + r * 512)];
        if (S > 1) {
            const int   jq = j & (S - 1);
            const float K  = (DIR > 0 ? -6.2831853071795865f : 6.2831853071795865f)
                             / (16.0f * (float)S);
            float ss, cc;
            __sincosf(K * (float)jq, &ss, &cc);
            float2 w1 = make_float2(cc, ss);
            float2 w2 = cmul(w1, w1);
            float2 w4 = cmul(w2, w2);
            float2 w8 = cmul(w4, w4);
            v[8] = cmul(v[8], w8);
            float2 w = w1;
            #pragma unroll
            for (int s = 1; s < 8; s++) {
                v[s]     = cmul(v[s], w);
                v[s + 8] = cmul(cmul(v[s + 8], w8), w);
                if (s < 7) w = cmul(w, w1);
            }
        }
        dft16<DIR>(v);
    }
    BARH(half);
    if (act) {
        const int jq   = j & (S - 1);
        const int base = jq + (j / S) * (S * 16);
        #pragma unroll
        for (int o = 0; o < 16; o++) {
            int slot = ((o & 3) << 2) | (o >> 2);
            buf[SWZ(base + S * o)] = v[slot];
        }
    }
    BARH(half);
}

// Hermitian rebuild (surrogate: random phase; kept: identity spectrum).
__device__ __forceinline__ void rebuild(float2* __restrict__ buf, int ka, int kb,
                                        float2 phA, float2 phB,
                                        bool sA, bool sB) {
    const float TWO_PI = 6.283185307179586476925f;
    const float scale  = 0.25f / (float)FFT_N;
    float2 Za = buf[SWZ(ka)], Zb = buf[SWZ(kb)];
    float ax = Za.x + Zb.x, ay = Za.y - Zb.y;
    float bx = Za.y + Zb.y, by = Zb.x - Za.x;
    float h1x, h1y, h2x, h2y;
    if (sA) {
        float ampA = sqrtf(fmaf(ax, ax, ay * ay)) * scale;
        float sA1, cA1, sA2, cA2;
        __sincosf(TWO_PI * phA.x, &sA1, &cA1);
        __sincosf(TWO_PI * phA.y, &sA2, &cA2);
        h1x = ampA * (cA1 + cA2);  h1y = ampA * (sA1 - sA2);
    } else {
        h1x = ax * (2.0f * scale); h1y = ay * (2.0f * scale);
    }
    if (sB) {
        float ampB = sqrtf(fmaf(bx, bx, by * by)) * scale;
        float sB1, cB1, sB2, cB2;
        __sincosf(TWO_PI * phB.x, &sB1, &cB1);
        __sincosf(TWO_PI * phB.y, &sB2, &cB2);
        h2x = ampB * (cB1 + cB2);  h2y = ampB * (sB1 - sB2);
    } else {
        h2x = bx * (2.0f * scale); h2y = by * (2.0f * scale);
    }
    buf[SWZ(ka)] = make_float2(h1x - h2y, h1y + h2x);
    buf[SWZ(kb)] = make_float2(h1x + h2y, h2x - h1y);
}

// Shared middle+tail of the pipeline (identical in both kernels).
__device__ __forceinline__ void fft_body(float2* b0, float2* b1,
                                         const float4* p4, float4* o4,
                                         int tid, bool s0, bool s1, bool s2, bool s3,
                                         bool p0, bool p1) {
    // Forward FFT: radix-16 at S=2, 32, 512 (load pass already did r2 @ S=1).
    stage16_pair<2,   1>(b0, b1, tid, p0, p1);
    stage16_pair<32,  1>(b0, b1, tid, p0, p1);
    stage16_pair<512, 1>(b0, b1, tid, p0, p1);
    __syncthreads();

    // Spectrum rebuild (fixed-trip, unrolled for load batching).
    #pragma unroll
    for (int i = 0; i < 4; i++) {
        const int k  = tid + i * NT;
        const int nk = (FFT_N - k) & (FFT_N - 1);
        float4 pk  = p4[(size_t)k  * 16];
        float4 pnk = p4[(size_t)nk * 16];
        if (p0) rebuild(b0, k, nk, make_float2(pk.x, pnk.x), make_float2(pk.y, pnk.y), s0, s1);
        if (p1) rebuild(b1, k, nk, make_float2(pk.z, pnk.z), make_float2(pk.w, pnk.w), s2, s3);
    }
    if (tid == 0) {
        float4 pk = p4[(size_t)4096 * 16];
        if (p0) rebuild(b0, 4096, 4096, make_float2(pk.x, pk.x), make_float2(pk.y, pk.y), s0, s1);
        if (p1) rebuild(b1, 4096, 4096, make_float2(pk.z, pk.z), make_float2(pk.w, pk.w), s2, s3);
    }
    __syncthreads();

    // Inverse FFT: radix-16 x3.
    stage16_pair<1,   -1>(b0, b1, tid, p0, p1);
    stage16_pair<16,  -1>(b0, b1, tid, p0, p1);
    stage16_pair<256, -1>(b0, b1, tid, p0, p1);
    __syncthreads();

    // Final inverse radix-2 + float4 store.
    #pragma unroll
    for (int i = 0; i < FFT_N / 2 / NT; i++) {
        int j = tid + i * NT;
        float ss, cc;
        __sincosf((float)j * PI_OVER_4096, &ss, &cc);
        float2 w = make_float2(cc, ss);
        float2 y0, y1, z0, z1;
        if (p0) {
            float2 u0 = b0[SWZ(j)], u1 = cmul(b0[SWZ(j + 4096)], w);
            y0 = cadd(u0, u1);  y1 = csub(u0, u1);
        } else {
            y0 = b0[SWZ(j)];  y1 = b0[SWZ(j + 4096)];
        }
        if (p1) {
            float2 u0 = b1[SWZ(j)], u1 = cmul(b1[SWZ(j + 4096)], w);
            z0 = cadd(u0, u1);  z1 = csub(u0, u1);
        } else {
            z0 = b1[SWZ(j)];  z1 = b1[SWZ(j + 4096)];
        }
        o4[(size_t)j * 16]          = make_float4(y0.x, y0.y, z0.x, z0.y);
        o4[(size_t)(j + 4096) * 16] = make_float4(y1.x, y1.y, z1.x, z1.y);
    }
}

// ---------------- TMA variant: wave input via cp.async.bulk.tensor ----------
__global__ __launch_bounds__(NT, 1)
void surrogate_kernel_tma(const __grid_constant__ CUtensorMap tmap,
                          const float* __restrict__ wave,
                          const float* __restrict__ phases,
                          const float* __restrict__ mask,
                          float* __restrict__ out) {
    const int blk = blockIdx.x;
    const int b   = blk >> 4;
    const int c0  = (blk & 15) * 4;
    const int tid = threadIdx.x;

    const bool s0 = mask[b * CH + c0]     < 0.5f;
    const bool s1 = mask[b * CH + c0 + 1] < 0.5f;
    const bool s2 = mask[b * CH + c0 + 2] < 0.5f;
    const bool s3 = mask[b * CH + c0 + 3] < 0.5f;
    const bool p0 = s0 | s1;
    const bool p1 = s2 | s3;

    const float4* w4 = (const float4*)(wave   + (size_t)b * FFT_N * CH + c0);
    const float4* p4 = (const float4*)(phases + (size_t)b * FFT_N * CH + c0);
    float4*       o4 = (float4*)      (out    + (size_t)b * FFT_N * CH + c0);

    if (!p0 && !p1) {
        #pragma unroll 4
        for (int t = tid; t < FFT_N; t += NT)
            o4[(size_t)t * 16] = w4[(size_t)t * 16];
        return;
    }

    extern __shared__ char smraw[];
    float2* b0 = (float2*)smraw;
    float2* b1 = (float2*)(smraw + 65536);

    uint32_t smem_base;
    asm("{ .reg .u64 t; cvta.to.shared.u64 t, %1; cvt.u32.u64 %0, t; }"
        : "=r"(smem_base) : "l"(smraw));
    const uint32_t stg_addr  = smem_base + SM_STAGE_OFF;
    const uint32_t mbar_addr = smem_base + SM_MBAR_OFF;

    if (tid == 0) {
        asm volatile("mbarrier.init.shared.b64 [%0], 1;" :: "r"(mbar_addr)     : "memory");
        asm volatile("mbarrier.init.shared.b64 [%0], 1;" :: "r"(mbar_addr + 8) : "memory");
    }
    __syncthreads();

    const int x = c0 * 4;               // byte offset of this quad within the 256B row
    const int ybase = b * FFT_N;

    // Issue one group: 4 boxes of {16B x 256 rows} -> 16KB into staging buf.
    auto issue = [&](int g) {
        const uint32_t dst = stg_addr + (uint32_t)(g & 1) * 16384u;
        const uint32_t mb  = mbar_addr + (uint32_t)(g & 1) * 8u;
        asm volatile("mbarrier.arrive.expect_tx.shared.b64 _, [%0], %1;"
                     :: "r"(mb), "r"(16384) : "memory");
        const int ylo = ybase + g * 512;
        const int yhi = ybase + 4096 + g * 512;
        #pragma unroll
        for (int q = 0; q < 2; q++) {
            asm volatile(
                "cp.async.bulk.tensor.2d.shared::cta.global.tile.mbarrier::complete_tx::bytes "
                "[%0], [%1, {%2, %3}], [%4];"
                :: "r"(dst + q * 4096u), "l"(&tmap), "r"(x), "r"(ylo + q * 256), "r"(mb)
                : "memory");
            asm volatile(
                "cp.async.bulk.tensor.2d.shared::cta.global.tile.mbarrier::complete_tx::bytes "
                "[%0], [%1, {%2, %3}], [%4];"
                :: "r"(dst + 8192u + q * 4096u), "l"(&tmap), "r"(x), "r"(yhi + q * 256), "r"(mb)
                : "memory");
        }
    };

    if (tid == 0) issue(0);

    const int r    = tid & 511;
    const int half = tid >> 9;

    // Pipelined: TMA group g+1 overlaps compute of group g.
    for (int g = 0; g < 8; g++) {
        if (g < 7 && tid == 0) issue(g + 1);
        {   // wait group g (acquire)
            const uint32_t mb = mbar_addr + (uint32_t)(g & 1) * 8u;
            const uint32_t ph = (uint32_t)((g >> 1) & 1);
            asm volatile(
                "{\n\t.reg .pred P;\n"
                "W%=:\n\t"
                "mbarrier.try_wait.parity.acquire.cta.shared::cta.b64 P, [%0], %1;\n\t"
                "@P bra D%=;\n\t"
                "bra W%=;\n"
                "D%=:\n\t}"
                :: "r"(mb), "r"(ph) : "memory");
        }
        // Fused forward radix-2 (S=1, twiddle-free) from staging.
        const float4* stg = (const float4*)(smraw + SM_STAGE_OFF + (g & 1) * 16384);
        float4 ga = stg[r];
        float4 gb = stg[512 + r];
        const int t = g * 512 + r;
        if (half == 0) {
            if (p0) {
                b0[SWZ(2 * t)]     = make_float2(ga.x + gb.x, ga.y + gb.y);
                b0[SWZ(2 * t + 1)] = make_float2(ga.x - gb.x, ga.y - gb.y);
            } else {
                b0[SWZ(t)]         = make_float2(ga.x, ga.y);
                b0[SWZ(t + 4096)]  = make_float2(gb.x, gb.y);
            }
        } else {
            if (p1) {
                b1[SWZ(2 * t)]     = make_float2(ga.z + gb.z, ga.w + gb.w);
                b1[SWZ(2 * t + 1)] = make_float2(ga.z - gb.z, ga.w - gb.w);
            } else {
                b1[SWZ(t)]         = make_float2(ga.z, ga.w);
                b1[SWZ(t + 4096)]  = make_float2(gb.z, gb.w);
            }
        }
        __syncthreads();   // staging buf (g&1) reusable; also final join before stages
    }

    fft_body(b0, b1, p4, o4, tid, s0, s1, s2, s3, p0, p1);
}

// ---------------- LDG fallback: exact R14 structure --------------------------
__global__ __launch_bounds__(NT, 1)
void surrogate_kernel_ldg(const float* __restrict__ wave,
                          const float* __restrict__ phases,
                          const float* __restrict__ mask,
                          float* __restrict__ out) {
    const int blk = blockIdx.x;
    const int b   = blk >> 4;
    const int c0  = (blk & 15) * 4;
    const int tid = threadIdx.x;

    const bool s0 = mask[b * CH + c0]     < 0.5f;
    const bool s1 = mask[b * CH + c0 + 1] < 0.5f;
    const bool s2 = mask[b * CH + c0 + 2] < 0.5f;
    const bool s3 = mask[b * CH + c0 + 3] < 0.5f;
    const bool p0 = s0 | s1;
    const bool p1 = s2 | s3;

    const float4* w4 = (const float4*)(wave   + (size_t)b * FFT_N * CH + c0);
    const float4* p4 = (const float4*)(phases + (size_t)b * FFT_N * CH + c0);
    float4*       o4 = (float4*)      (out    + (size_t)b * FFT_N * CH + c0);

    if (!p0 && !p1) {
        #pragma unroll 4
        for (int t = tid; t < FFT_N; t += NT)
            o4[(size_t)t * 16] = w4[(size_t)t * 16];
        return;
    }

    extern __shared__ char smraw[];
    float2* b0 = (float2*)smraw;
    float2* b1 = (float2*)(smraw + 65536);

    #pragma unroll
    for (int i = 0; i < FFT_N / 2 / NT; i++) {
        int t = tid + i * NT;
        float4 ga = w4[(size_t)t * 16];
        float4 gb = w4[(size_t)(t + 4096) * 16];
        if (p0) {
            b0[SWZ(2 * t)]     = make_float2(ga.x + gb.x, ga.y + gb.y);
            b0[SWZ(2 * t + 1)] = make_float2(ga.x - gb.x, ga.y - gb.y);
        } else {
            b0[SWZ(t)]         = make_float2(ga.x, ga.y);
            b0[SWZ(t + 4096)]  = make_float2(gb.x, gb.y);
        }
        if (p1) {
            b1[SWZ(2 * t)]     = make_float2(ga.z + gb.z, ga.w + gb.w);
            b1[SWZ(2 * t + 1)] = make_float2(ga.z - gb.z, ga.w - gb.w);
        } else {
            b1[SWZ(t)]         = make_float2(ga.z, ga.w);
            b1[SWZ(t + 4096)]  = make_float2(gb.z, gb.w);
        }
    }
    __syncthreads();

    fft_body(b0, b1, p4, o4, tid, s0, s1, s2, s3, p0, p1);
}

extern "C" void kernel_launch(void* const* d_in, const int* in_sizes, int n_in,
                              void* d_out, int out_size) {
    const float* wave   = (const float*)d_in[0];
    const float* phases = (const float*)d_in[1];
    const float* maskp  = (const float*)d_in[2];
    float* out = (float*)d_out;

    const int B = in_sizes[0] / (FFT_N * CH);

    // Try to build a TMA descriptor for the wave tensor (rows of 256B; the
    // kernel's box is the quad's 16B slice x 256 rows). Fall back to LDG.
    typedef CUresult (*PFN_encode)(CUtensorMap*, CUtensorMapDataType, cuuint32_t,
                                   void*, const cuuint64_t*, const cuuint64_t*,
                                   const cuuint32_t*, const cuuint32_t*,
                                   CUtensorMapInterleave, CUtensorMapSwizzle,
                                   CUtensorMapL2promotion, CUtensorMapFloatOOBfill);
    CUtensorMap tmap;
    bool use_tma = false;
    {
        void* fn = nullptr;
        cudaDriverEntryPointQueryResult qr;
        if (cudaGetDriverEntryPoint("cuTensorMapEncodeTiled", &fn,
                                    cudaEnableDefault, &qr) == cudaSuccess && fn) {
            PFN_encode enc = (PFN_encode)fn;
            cuuint64_t dims[2]    = {(cuuint64_t)(CH * 4), (cuuint64_t)B * FFT_N};
            cuuint64_t strides[1] = {(cuuint64_t)(CH * 4)};
            cuuint32_t box[2]     = {16, 256};
            cuuint32_t es[2]      = {1, 1};
            use_tma = (enc(&tmap, CU_TENSOR_MAP_DATA_TYPE_UINT8, 2, (void*)wave,
                           dims, strides, box, es,
                           CU_TENSOR_MAP_INTERLEAVE_NONE, CU_TENSOR_MAP_SWIZZLE_NONE,
                           CU_TENSOR_MAP_L2_PROMOTION_L2_128B,
                           CU_TENSOR_MAP_FLOAT_OOB_FILL_NONE) == CUDA_SUCCESS);
        }
    }

    if (use_tma) {
        cudaFuncSetAttribute(surrogate_kernel_tma,
                             cudaFuncAttributeMaxDynamicSharedMemorySize, SM_TMA_TOTAL);
        surrogate_kernel_tma<<<B * (CH / 4), NT, SM_TMA_TOTAL>>>(tmap, wave, phases, maskp, out);
    } else {
        const int smem = 2 * FFT_N * (int)sizeof(float2);
        cudaFuncSetAttribute(surrogate_kernel_ldg,
                             cudaFuncAttributeMaxDynamicSharedMemorySize, smem);
        surrogate_kernel_ldg<<<B * (CH / 4), NT, smem>>>(wave, phases, maskp, out);
    }
}